// round 16
// baseline (speedup 1.0000x reference)
#include <cuda_runtime.h>
#include <cuda_fp16.h>
#include <stdint.h>

#define N_NODES 50000
#define D       128
#define EH      500000
#define ES      250000
#define NCLS    47
#define E_TOT   (2 * (EH + ES))

typedef unsigned long long ull;

// ---------------- scratch (device globals; no runtime allocation) ----------------
__device__ int    g_cnt[4 * N_NODES];
__device__ int    g_off[4 * (N_NODES + 1)];
__device__ int    g_cur[4 * N_NODES];
__device__ int    g_eidx[E_TOT];
__device__ float  g_neigh0[N_NODES * D];
__device__ float  g_neigh1[N_NODES * D];
__device__ float  g_H1[N_NODES * D];
__device__ __half g_hb0h[N_NODES * D];    // fp16 copy of hbar0
__device__ __half g_hb1h[N_NODES * D];    // fp16 copy of hbar1
__device__ __half g_Hd16[N_NODES * D];    // fp16 (H - HBar) for current layer

__device__ __forceinline__ int eidx_base(int p) {
    return p == 0 ? 0 : p == 1 ? EH : p == 2 ? (EH + ES) : (2 * EH + ES);
}

// ---------------- fp16 pack helpers ----------------
__device__ __forceinline__ uint2 pack_h4(float a, float b, float c, float d) {
    __half2 p0 = __floats2half2_rn(a, b);
    __half2 p1 = __floats2half2_rn(c, d);
    uint2 u;
    u.x = *(uint32_t*)&p0;
    u.y = *(uint32_t*)&p1;
    return u;
}

// ---------------- K1: count || (hdelta0 + cvt hbar0) || cvt hbar1 ----------------
#define GE_BLOCKS  ((E_TOT + 255) / 256)           // 5860
#define GEL_BLOCKS ((N_NODES * D / 4 + 255) / 256) // 6250

__global__ void count_cvt_kernel(const int* __restrict__ hd0, const int* __restrict__ sd0,
                                 const int* __restrict__ hd1, const int* __restrict__ sd1,
                                 const float* __restrict__ x, const float* __restrict__ hbar0,
                                 const float* __restrict__ hbar1) {
    int b = blockIdx.x;
    if (b < GE_BLOCKS) {
        int i = b * blockDim.x + threadIdx.x;
        if (i >= E_TOT) return;
        int pair, off;
        const int* p;
        if (i < EH)               { pair = 0; p = hd0; off = i; }
        else if (i < EH + ES)     { pair = 1; p = sd0; off = i - EH; }
        else if (i < 2 * EH + ES) { pair = 2; p = hd1; off = i - EH - ES; }
        else                      { pair = 3; p = sd1; off = i - 2 * EH - ES; }
        atomicAdd(&g_cnt[pair * N_NODES + __ldg(p + off)], 1);
    } else if (b < GE_BLOCKS + GEL_BLOCKS) {
        int i = (b - GE_BLOCKS) * blockDim.x + threadIdx.x;
        if (i >= N_NODES * D / 4) return;
        float4 a = __ldg((const float4*)x + i);
        float4 h = __ldg((const float4*)hbar0 + i);
        ((uint2*)g_Hd16)[i] = pack_h4(a.x - h.x, a.y - h.y, a.z - h.z, a.w - h.w);
        ((uint2*)g_hb0h)[i] = pack_h4(h.x, h.y, h.z, h.w);
    } else {
        int i = (b - GE_BLOCKS - GEL_BLOCKS) * blockDim.x + threadIdx.x;
        if (i >= N_NODES * D / 4) return;
        float4 h = __ldg((const float4*)hbar1 + i);
        ((uint2*)g_hb1h)[i] = pack_h4(h.x, h.y, h.z, h.w);
    }
}

// ---------------- scan (4 blocks, one per pair) ----------------
__global__ void scan_kernel() {
    const int p = blockIdx.x;
    int* cnt = g_cnt + p * N_NODES;
    int* off = g_off + p * (N_NODES + 1);
    int* cur = g_cur + p * N_NODES;
    const int T = 1024;
    const int C = (N_NODES + T - 1) / T;
    __shared__ int part[T];
    int t = threadIdx.x;
    int base = t * C;
    int s = 0;
#pragma unroll 1
    for (int i = 0; i < C; i++) {
        int j = base + i;
        if (j < N_NODES) s += cnt[j];
    }
    part[t] = s;
    __syncthreads();
    for (int d2 = 1; d2 < T; d2 <<= 1) {
        int v = (t >= d2) ? part[t - d2] : 0;
        __syncthreads();
        part[t] += v;
        __syncthreads();
    }
    int run = part[t] - s;
#pragma unroll 1
    for (int i = 0; i < C; i++) {
        int j = base + i;
        if (j < N_NODES) {
            off[j] = run;
            cur[j] = run;
            run += cnt[j];
        }
    }
    if (t == T - 1) off[N_NODES] = part[t];
}

__global__ void bucket_all_kernel(const int* __restrict__ hs0, const int* __restrict__ hd0,
                                  const int* __restrict__ ss0, const int* __restrict__ sd0,
                                  const int* __restrict__ hs1, const int* __restrict__ hd1,
                                  const int* __restrict__ ss1, const int* __restrict__ sd1) {
    int i = blockIdx.x * blockDim.x + threadIdx.x;
    if (i >= E_TOT) return;
    int pair, off;
    const int *ps, *pd;
    if (i < EH)               { pair = 0; ps = hs0; pd = hd0; off = i; }
    else if (i < EH + ES)     { pair = 1; ps = ss0; pd = sd0; off = i - EH; }
    else if (i < 2 * EH + ES) { pair = 2; ps = hs1; pd = hd1; off = i - EH - ES; }
    else                      { pair = 3; ps = ss1; pd = sd1; off = i - 2 * EH - ES; }
    int d = __ldg(pd + off);
    int pos = atomicAdd(&g_cur[pair * N_NODES + d], 1);
    g_eidx[eidx_base(pair) + pos] = __ldg(ps + off);
}

// ---------------- paired-row fp16 gather: 2 edges per LDG.128 ----------------
// Warp split: half = lane>>4 handles edges e0+half, e0+2+half, ...; sub = lane&15
// covers halves [8*sub, 8*sub+8) of the row. Cross-half combine via shfl_xor(16).
struct F8 { float4 a, b; };

__device__ __forceinline__ void acc8(float4& a, float4& b, uint4 u) {
    __half2 h0 = *(__half2*)&u.x, h1 = *(__half2*)&u.y;
    __half2 h2 = *(__half2*)&u.z, h3 = *(__half2*)&u.w;
    float2 f0 = __half22float2(h0), f1 = __half22float2(h1);
    float2 f2 = __half22float2(h2), f3 = __half22float2(h3);
    a.x += f0.x; a.y += f0.y; a.z += f1.x; a.w += f1.y;
    b.x += f2.x; b.y += f2.y; b.z += f3.x; b.w += f3.y;
}
__device__ __forceinline__ void f4_add(float4& a, float4 v) {
    a.x += v.x; a.y += v.y; a.z += v.z; a.w += v.w;
}
__device__ __forceinline__ void xor16(float4& a) {
    a.x += __shfl_xor_sync(0xFFFFFFFF, a.x, 16);
    a.y += __shfl_xor_sync(0xFFFFFFFF, a.y, 16);
    a.z += __shfl_xor_sync(0xFFFFFFFF, a.z, 16);
    a.w += __shfl_xor_sync(0xFFFFFFFF, a.w, 16);
}

__device__ __forceinline__ F8 gather8(const __half* __restrict__ feat,
                                      const int* __restrict__ idx,
                                      int e0, int e1, int half, int sub) {
    float4 a0 = make_float4(0,0,0,0), b0 = a0, a1 = a0, b1 = a0;
    int e = e0;
    for (; e + 4 <= e1; e += 4) {
        int i0 = __ldg(idx + e + half);
        int i1 = __ldg(idx + e + 2 + half);
        uint4 u0 = __ldg((const uint4*)(feat + (size_t)i0 * D) + sub);
        uint4 u1 = __ldg((const uint4*)(feat + (size_t)i1 * D) + sub);
        acc8(a0, b0, u0);
        acc8(a1, b1, u1);
    }
    if (e + 2 <= e1) {
        int i0 = __ldg(idx + e + half);
        uint4 u0 = __ldg((const uint4*)(feat + (size_t)i0 * D) + sub);
        acc8(a0, b0, u0);
        e += 2;
    }
    if (e < e1 && half == 0) {       // odd leftover: half-0 lanes only
        int i0 = __ldg(idx + e);
        uint4 u0 = __ldg((const uint4*)(feat + (size_t)i0 * D) + sub);
        acc8(a0, b0, u0);
    }
    f4_add(a0, a1); f4_add(b0, b1);
    F8 r; r.a = a0; r.b = b0;
    return r;
}

// ---------------- K4: agg0 (pairs 0,1 -> g_neigh0)  ||  agg1_hist (pair 2 -> g_neigh1) ----
#define GAGG_BLOCKS ((N_NODES * 32 + 255) / 256)   // 6250

__global__ void agg_combined_kernel() {
    int b = blockIdx.x;
    int g = (b < GAGG_BLOCKS ? b : b - GAGG_BLOCKS) * blockDim.x + threadIdx.x;
    int w = g >> 5, lane = g & 31;
    if (w >= N_NODES) return;
    const int half = lane >> 4;
    const int sub  = lane & 15;

    if (b < GAGG_BLOCKS) {
        const int* offH = g_off + 0 * (N_NODES + 1);
        const int* offD = g_off + 1 * (N_NODES + 1);
        int h0 = __ldg(offH + w), h1 = __ldg(offH + w + 1);
        int d0 = __ldg(offD + w), d1 = __ldg(offD + w + 1);
        F8 h = gather8(g_hb0h, g_eidx + eidx_base(0), h0, h1, half, sub);
        F8 d = gather8(g_Hd16, g_eidx + eidx_base(1), d0, d1, half, sub);
        xor16(h.a); xor16(h.b); xor16(d.a); xor16(d.b);
        float invh = 1.f / fmaxf((float)(h1 - h0), 1.f);
        float invd = 1.f / fmaxf((float)(d1 - d0), 1.f);
        if (half == 0) {
            float4 o0 = make_float4(h.a.x * invh + d.a.x * invd, h.a.y * invh + d.a.y * invd,
                                    h.a.z * invh + d.a.z * invd, h.a.w * invh + d.a.w * invd);
            float4 o1 = make_float4(h.b.x * invh + d.b.x * invd, h.b.y * invh + d.b.y * invd,
                                    h.b.z * invh + d.b.z * invd, h.b.w * invh + d.b.w * invd);
            float4* dst = (float4*)(g_neigh0 + (size_t)w * D + sub * 8);
            dst[0] = o0;
            dst[1] = o1;
        }
    } else {
        const int* offH = g_off + 2 * (N_NODES + 1);
        int h0 = __ldg(offH + w), h1 = __ldg(offH + w + 1);
        F8 h = gather8(g_hb1h, g_eidx + eidx_base(2), h0, h1, half, sub);
        xor16(h.a); xor16(h.b);
        float invh = 1.f / fmaxf((float)(h1 - h0), 1.f);
        if (half == 0) {
            float4 o0 = make_float4(h.a.x * invh, h.a.y * invh, h.a.z * invh, h.a.w * invh);
            float4 o1 = make_float4(h.b.x * invh, h.b.y * invh, h.b.z * invh, h.b.w * invh);
            float4* dst = (float4*)(g_neigh1 + (size_t)w * D + sub * 8);
            dst[0] = o0;
            dst[1] = o1;
        }
    }
}

// ---------------- agg1_delta: g_neigh1 += mean over pair 3 of g_Hd16 ----------------
__global__ void agg1_delta_kernel() {
    int g = blockIdx.x * blockDim.x + threadIdx.x;
    int w = g >> 5, lane = g & 31;
    if (w >= N_NODES) return;
    const int* offD = g_off + 3 * (N_NODES + 1);
    int d0 = __ldg(offD + w), d1 = __ldg(offD + w + 1);
    if (d0 == d1) return;
    const int half = lane >> 4;
    const int sub  = lane & 15;
    F8 d = gather8(g_Hd16, g_eidx + eidx_base(3), d0, d1, half, sub);
    xor16(d.a); xor16(d.b);
    float invd = 1.f / (float)(d1 - d0);
    if (half == 0) {
        float4* dst = (float4*)(g_neigh1 + (size_t)w * D + sub * 8);
        float4 o0 = dst[0], o1 = dst[1];
        o0.x += d.a.x * invd; o0.y += d.a.y * invd;
        o0.z += d.a.z * invd; o0.w += d.a.w * invd;
        o1.x += d.b.x * invd; o1.y += d.b.y * invd;
        o1.z += d.b.z * invd; o1.w += d.b.w * invd;
        dst[0] = o0;
        dst[1] = o1;
    }
}

// ---------------- HMMA helpers ----------------
__device__ __forceinline__ uint32_t smem_u32(const void* p) {
    uint32_t a;
    asm("{ .reg .u64 t; cvta.to.shared.u64 t, %1; cvt.u32.u64 %0, t; }" : "=r"(a) : "l"(p));
    return a;
}
__device__ __forceinline__ void ldmatrix_x4(uint32_t& r0, uint32_t& r1,
                                            uint32_t& r2, uint32_t& r3, uint32_t addr) {
    asm volatile("ldmatrix.sync.aligned.m8n8.x4.shared.b16 {%0,%1,%2,%3}, [%4];"
                 : "=r"(r0), "=r"(r1), "=r"(r2), "=r"(r3) : "r"(addr));
}
__device__ __forceinline__ void mma_16816(float* c, const uint32_t* a, const uint32_t* b) {
    asm volatile("mma.sync.aligned.m16n8k16.row.col.f32.f16.f16.f32 "
                 "{%0,%1,%2,%3}, {%4,%5,%6,%7}, {%8,%9}, {%0,%1,%2,%3};"
                 : "+f"(c[0]), "+f"(c[1]), "+f"(c[2]), "+f"(c[3])
                 : "r"(a[0]), "r"(a[1]), "r"(a[2]), "r"(a[3]), "r"(b[0]), "r"(b[1]));
}

// ---------------- HMMA GEMM + bias + ReLU (fp16 operands, fp32 accum) ----------------
template <int LAYER, int DOUT, int BM, int BN, int WARPS_M, int WARPS_N,
          int NTILES, int MAXB>
__global__ void __launch_bounds__(256, MAXB)
gemm_hmma_kernel(const float* __restrict__ Hext,
                 const float* __restrict__ W,
                 const float* __restrict__ bias,
                 const float* __restrict__ hbar1,   // layer0 only
                 float* __restrict__ outext) {
    constexpr int BK = 32, K = 2 * D, NK = K / BK;
    constexpr int WM = BM / WARPS_M;
    constexpr int WN = BN / WARPS_N;
    constexpr int MI = WM / 16;
    constexpr int NJ = WN / 8;
    constexpr int PITCH = BK + 8;
    constexpr int ASTRIDE = BM * PITCH;
    constexpr int BSTRIDE = BN * PITCH;
    constexpr int NA = (BM * BK) / (256 * 4);
    constexpr int NB = (BN * BK) / (256 * 4);

    const float* H     = (LAYER == 0) ? Hext     : g_H1;
    const float* neigh = (LAYER == 0) ? g_neigh0 : g_neigh1;
    float* out         = (LAYER == 0) ? g_H1     : outext;

    extern __shared__ __half smemh[];
    __half* AsBase = smemh;
    __half* BsBase = smemh + 2 * ASTRIDE;

    const int t      = threadIdx.x;
    const int lane   = t & 31;
    const int warp   = t >> 5;
    const int warp_m = warp % WARPS_M;
    const int warp_n = warp / WARPS_M;
    const int tile   = (NTILES == 1) ? blockIdx.x : (blockIdx.x / NTILES);
    const int nb0    = (NTILES == 1) ? 0 : (blockIdx.x % NTILES) * BN;
    const int row0   = tile * BM;

    float4 pa[NA], pb[NB];

    auto load_tile = [&](int kit) {
        const int k0 = kit * BK;
        const float* Asrc = (k0 < D) ? (H + k0) : (neigh + (k0 - D));
#pragma unroll
        for (int v = 0; v < NA; v++) {
            int id = v * 256 + t;
            int m  = id >> 3;
            int kq = id & 7;
            int r  = min(row0 + m, N_NODES - 1);
            pa[v] = __ldg((const float4*)(Asrc + (size_t)r * D) + kq);
        }
#pragma unroll
        for (int v = 0; v < NB; v++) {
            int id = v * 256 + t;
            int n  = nb0 + (id >> 3);
            int kq = id & 7;
            pb[v] = (n < DOUT) ? __ldg((const float4*)(W + (size_t)n * K + k0) + kq)
                               : make_float4(0.f, 0.f, 0.f, 0.f);
        }
    };
    auto store_tile = [&](int buf) {
        __half* As = AsBase + buf * ASTRIDE;
        __half* Bs = BsBase + buf * BSTRIDE;
#pragma unroll
        for (int v = 0; v < NA; v++) {
            int id = v * 256 + t;
            int m  = id >> 3;
            int kq = id & 7;
            *(uint2*)(As + m * PITCH + kq * 4) = pack_h4(pa[v].x, pa[v].y, pa[v].z, pa[v].w);
        }
#pragma unroll
        for (int v = 0; v < NB; v++) {
            int id = v * 256 + t;
            int n  = id >> 3;
            int kq = id & 7;
            *(uint2*)(Bs + n * PITCH + kq * 4) = pack_h4(pb[v].x, pb[v].y, pb[v].z, pb[v].w);
        }
    };

    float acc[MI][NJ][4];
#pragma unroll
    for (int i = 0; i < MI; i++)
#pragma unroll
        for (int j = 0; j < NJ; j++)
#pragma unroll
            for (int q = 0; q < 4; q++) acc[i][j][q] = 0.f;

    load_tile(0);
    store_tile(0);
    load_tile(1);
    __syncthreads();

    for (int kit = 0; kit < NK; kit++) {
        if (kit + 1 < NK) store_tile((kit + 1) & 1);
        if (kit + 2 < NK) load_tile(kit + 2);

        const __half* As = AsBase + (kit & 1) * ASTRIDE;
        const __half* Bs = BsBase + (kit & 1) * BSTRIDE;
        const uint32_t asb = smem_u32(As);
        const uint32_t bsb = smem_u32(Bs);

#pragma unroll
        for (int ks = 0; ks < BK / 16; ks++) {
            uint32_t afr[MI][4];
#pragma unroll
            for (int mi = 0; mi < MI; mi++) {
                int m = warp_m * WM + mi * 16 + (lane & 15);
                uint32_t addr = asb + (m * PITCH + ks * 16 + (lane >> 4) * 8) * 2;
                ldmatrix_x4(afr[mi][0], afr[mi][1], afr[mi][2], afr[mi][3], addr);
            }
            uint32_t bfr[NJ][2];
#pragma unroll
            for (int nj2 = 0; nj2 < NJ / 2; nj2++) {
                int n = warp_n * WN + nj2 * 16 + (lane & 7) + ((lane >> 4) << 3);
                uint32_t addr = bsb + (n * PITCH + ks * 16 + ((lane >> 3) & 1) * 8) * 2;
                uint32_t r0, r1, r2, r3;
                ldmatrix_x4(r0, r1, r2, r3, addr);
                bfr[2 * nj2 + 0][0] = r0; bfr[2 * nj2 + 0][1] = r1;
                bfr[2 * nj2 + 1][0] = r2; bfr[2 * nj2 + 1][1] = r3;
            }
#pragma unroll
            for (int mi = 0; mi < MI; mi++)
#pragma unroll
                for (int nj = 0; nj < NJ; nj++)
                    mma_16816(acc[mi][nj], afr[mi], bfr[nj]);
        }
        __syncthreads();
    }

#pragma unroll
    for (int mi = 0; mi < MI; mi++) {
#pragma unroll
        for (int nj = 0; nj < NJ; nj++) {
            int c  = nb0 + warp_n * WN + nj * 8 + 2 * (lane & 3);
            int r0 = row0 + warp_m * WM + mi * 16 + (lane >> 2);
            int r1 = r0 + 8;
            float b0 = (c     < DOUT) ? __ldg(bias + c)     : 0.f;
            float b1 = (c + 1 < DOUT) ? __ldg(bias + c + 1) : 0.f;
            float v00 = fmaxf(acc[mi][nj][0] + b0, 0.f);
            float v01 = fmaxf(acc[mi][nj][1] + b1, 0.f);
            float v10 = fmaxf(acc[mi][nj][2] + b0, 0.f);
            float v11 = fmaxf(acc[mi][nj][3] + b1, 0.f);
            if (LAYER == 0) {
                if (r0 < N_NODES) {
                    *(float2*)(out + (size_t)r0 * DOUT + c) = make_float2(v00, v01);
                    float2 hb = *(const float2*)(hbar1 + (size_t)r0 * D + c);
                    __half2 hd = __floats2half2_rn(v00 - hb.x, v01 - hb.y);
                    *(__half2*)(g_Hd16 + (size_t)r0 * D + c) = hd;
                }
                if (r1 < N_NODES) {
                    *(float2*)(out + (size_t)r1 * DOUT + c) = make_float2(v10, v11);
                    float2 hb = *(const float2*)(hbar1 + (size_t)r1 * D + c);
                    __half2 hd = __floats2half2_rn(v10 - hb.x, v11 - hb.y);
                    *(__half2*)(g_Hd16 + (size_t)r1 * D + c) = hd;
                }
            } else {
                if (r0 < N_NODES) {
                    if (c     < DOUT) out[(size_t)r0 * DOUT + c]     = v00;
                    if (c + 1 < DOUT) out[(size_t)r0 * DOUT + c + 1] = v01;
                }
                if (r1 < N_NODES) {
                    if (c     < DOUT) out[(size_t)r1 * DOUT + c]     = v10;
                    if (c + 1 < DOUT) out[(size_t)r1 * DOUT + c + 1] = v11;
                }
            }
        }
    }
}

// ---------------- launch ----------------
extern "C" void kernel_launch(void* const* d_in, const int* in_sizes, int n_in,
                              void* d_out, int out_size) {
    const float* x     = (const float*)d_in[0];
    const float* hbar0 = (const float*)d_in[1];
    const float* hbar1 = (const float*)d_in[2];
    const float* W0    = (const float*)d_in[3];
    const float* b0    = (const float*)d_in[4];
    const float* W1    = (const float*)d_in[5];
    const float* b1    = (const float*)d_in[6];
    const int* hsrc0   = (const int*)d_in[7];
    const int* hdst0   = (const int*)d_in[8];
    const int* ssrc0   = (const int*)d_in[9];
    const int* sdst0   = (const int*)d_in[10];
    const int* hsrc1   = (const int*)d_in[11];
    const int* hdst1   = (const int*)d_in[12];
    const int* ssrc1   = (const int*)d_in[13];
    const int* sdst1   = (const int*)d_in[14];
    float* out = (float*)d_out;

    const int SM0 = 2 * (128 + 64) * 40 * 2;   // 30720 B
    const int SM1 = 2 * (64 + 64) * 40 * 2;    // 20480 B
    cudaFuncSetAttribute((const void*)gemm_hmma_kernel<0, 128, 128, 64, 4, 2, 2, 2>,
                         cudaFuncAttributeMaxDynamicSharedMemorySize, SM0);
    cudaFuncSetAttribute((const void*)gemm_hmma_kernel<1, NCLS, 64, 64, 2, 4, 1, 3>,
                         cudaFuncAttributeMaxDynamicSharedMemorySize, SM1);

    // ---- K0: zero counters ----
    void* cnt_ptr = nullptr;
    cudaGetSymbolAddress(&cnt_ptr, g_cnt);
    cudaMemsetAsync(cnt_ptr, 0, sizeof(int) * 4 * N_NODES);

    // ---- K1: count || (hdelta0+cvt hbar0) || cvt hbar1 ----
    count_cvt_kernel<<<GE_BLOCKS + 2 * GEL_BLOCKS, 256>>>(hdst0, sdst0, hdst1, sdst1,
                                                          x, hbar0, hbar1);

    // ---- K2/K3: scan + bucket ----
    scan_kernel<<<4, 1024>>>();
    bucket_all_kernel<<<GE_BLOCKS, 256>>>(hsrc0, hdst0, ssrc0, sdst0,
                                          hsrc1, hdst1, ssrc1, sdst1);

    // ---- K4: agg0 || agg1_hist (paired-row fp16 gathers) ----
    agg_combined_kernel<<<2 * GAGG_BLOCKS, 256>>>();

    // ---- K5: gemm0 HMMA, BM=128 x BN=64, N split in 2 (grid 782), fused fp16 hdelta1 ----
    gemm_hmma_kernel<0, 128, 128, 64, 4, 2, 2, 2>
        <<<((N_NODES + 127) / 128) * 2, 256, SM0>>>(x, W0, b0, hbar1, nullptr);

    // ---- K6: agg1_delta (paired-row fp16 gather) ----
    agg1_delta_kernel<<<GAGG_BLOCKS, 256>>>();

    // ---- K7: gemm1 HMMA, BM=64 x BN=64 (grid 782) ----
    gemm_hmma_kernel<1, NCLS, 64, 64, 2, 4, 1, 3>
        <<<(N_NODES + 63) / 64, 256, SM1>>>(nullptr, W1, b1, nullptr, out);
}